// round 15
// baseline (speedup 1.0000x reference)
#include <cuda_runtime.h>
#include <math.h>

#define E_MAX 160000
#define N_MAX 10000

// scratch (static __device__ -> allowed, no allocations)
__device__ float g_mix[(size_t)E_MAX * 256];   // per-edge radial MLP output
__device__ float g_hA[(size_t)64 * E_MAX];     // transposed activations [k][e]
__device__ float g_hB[(size_t)64 * E_MAX];
__device__ float g_y[(size_t)E_MAX * 16];      // per-edge Y_1(3),Y_2(5),Y_3(7),pad
__device__ int   g_count[N_MAX + 1];
__device__ int   g_start[N_MAX + 2];
__device__ int   g_cursor[N_MAX + 1];
__device__ int   g_esort[E_MAX];

// ---------------- packed f32x2 helpers (exact fp32, 2 FMAs / issue) ----------
__device__ __forceinline__ unsigned long long splat2(float x) {
    unsigned long long r;
    unsigned u = __float_as_uint(x);
    asm("mov.b64 %0, {%1, %1};" : "=l"(r) : "r"(u));
    return r;
}
__device__ __forceinline__ void fma2(unsigned long long& acc,
                                     unsigned long long a, unsigned long long b) {
    asm("fma.rn.f32x2 %0, %1, %2, %0;" : "+l"(acc) : "l"(a), "l"(b));
}
__device__ __forceinline__ float2 unpack2(unsigned long long v) {
    unsigned lo, hi;
    asm("mov.b64 {%0, %1}, %2;" : "=r"(lo), "=r"(hi) : "l"(v));
    return make_float2(__uint_as_float(lo), __uint_as_float(hi));
}
__device__ __forceinline__ float silu(float v) {
    return v * (1.0f / (1.0f + __expf(-v)));
}

// ---------------------------------------------------------------- zero counts
__global__ void k_zero(int n) {
    int i = blockIdx.x * blockDim.x + threadIdx.x;
    if (i <= n) g_count[i] = 0;
}

// ------------------------------------------- spherical harmonics + histogram
__global__ void k_y_hist(const float* __restrict__ vectors,
                         const int* __restrict__ receivers, int E) {
    int e = blockIdx.x * blockDim.x + threadIdx.x;
    if (e >= E) return;
    float x = vectors[3 * e + 0];
    float y = vectors[3 * e + 1];
    float z = vectors[3 * e + 2];
    float n2 = x * x + y * y + z * z;
    float inv = 1.0f / (sqrtf(n2) + 1e-12f);
    x *= inv; y *= inv; z *= inv;

    const float s3  = 1.7320508075688772f;
    const float s5  = 2.23606797749979f;
    const float s15 = 3.872983346207417f;
    const float c33 = 2.091650066335189f;
    const float c32 = 10.246950765959598f;
    const float c31 = 1.6201851746019651f;
    const float c30 = 1.3228756555322954f;

    float yv[16];
    yv[0] = s3 * y;  yv[1] = s3 * z;  yv[2] = s3 * x;
    yv[3] = s15 * x * y;
    yv[4] = s15 * y * z;
    yv[5] = 0.5f * s5 * (3.0f * z * z - 1.0f);
    yv[6] = s15 * x * z;
    yv[7] = 0.5f * s15 * (x * x - y * y);
    yv[8]  = c33 * y * (3.0f * x * x - y * y);
    yv[9]  = c32 * x * y * z;
    yv[10] = c31 * y * (5.0f * z * z - 1.0f);
    yv[11] = c30 * z * (5.0f * z * z - 3.0f);
    yv[12] = c31 * x * (5.0f * z * z - 1.0f);
    yv[13] = 0.5f * c32 * z * (x * x - y * y);
    yv[14] = c33 * x * (x * x - 3.0f * y * y);
    yv[15] = 1.0f;

    float4* o = (float4*)(g_y + (size_t)e * 16);
    o[0] = make_float4(yv[0], yv[1], yv[2], yv[3]);
    o[1] = make_float4(yv[4], yv[5], yv[6], yv[7]);
    o[2] = make_float4(yv[8], yv[9], yv[10], yv[11]);
    o[3] = make_float4(yv[12], yv[13], yv[14], yv[15]);

    atomicAdd(&g_count[receivers[e]], 1);
}

// ---------------------------------------------------------------- CSR scan
__global__ void k_scan(int n, int E) {
    __shared__ int sums[1024];
    int t = threadIdx.x;
    int chunk = (n + 1023) >> 10;
    int b = t * chunk;
    int eidx = min(b + chunk, n);
    int s = 0;
    for (int i = b; i < eidx; i++) s += g_count[i];
    sums[t] = s;
    __syncthreads();
    for (int off = 1; off < 1024; off <<= 1) {
        int v = (t >= off) ? sums[t - off] : 0;
        __syncthreads();
        sums[t] += v;
        __syncthreads();
    }
    int pre = (t > 0) ? sums[t - 1] : 0;
    for (int i = b; i < eidx; i++) {
        g_start[i]  = pre;
        g_cursor[i] = pre;
        pre += g_count[i];
    }
    if (t == 1023) g_start[n] = E;
}

// ---------------------------------------------------------------- scatter
__global__ void k_scatter(const int* __restrict__ receivers, int E) {
    int e = blockIdx.x * blockDim.x + threadIdx.x;
    if (e >= E) return;
    int p = atomicAdd(&g_cursor[receivers[e]], 1);
    g_esort[p] = e;
}

// -------------------------------------------------------------- MLP layers

// layer 1: 8 -> 64 (j-half per blockIdx.y), silu -> g_hA  (R12 structure)
__global__ void __launch_bounds__(256, 4)
k_l1(const float* __restrict__ radial, const float* __restrict__ w1, int E) {
    __shared__ float ws[8 * 32];
    int tid = threadIdx.x;
    int j0 = blockIdx.y * 32;
    if (tid < 256) {
        int k = tid >> 5, j = tid & 31;
        ws[tid] = w1[k * 64 + j0 + j] * 0.35355339059327379f;
    }
    __syncthreads();
    int e = blockIdx.x * 256 + tid;
    if (e >= E) return;

    const float4* rp = (const float4*)(radial + (size_t)e * 8);
    float4 a0 = __ldg(rp), a1 = __ldg(rp + 1);
    float r[8] = {a0.x, a0.y, a0.z, a0.w, a1.x, a1.y, a1.z, a1.w};

    unsigned long long acc[16];
    #pragma unroll
    for (int q = 0; q < 16; q++) acc[q] = 0ULL;
    #pragma unroll
    for (int k = 0; k < 8; k++) {
        unsigned long long a = splat2(r[k]);
        const ulonglong2* wp = (const ulonglong2*)(ws + k * 32);
        #pragma unroll
        for (int q = 0; q < 8; q++) {
            ulonglong2 w = wp[q];
            fma2(acc[2 * q],     a, w.x);
            fma2(acc[2 * q + 1], a, w.y);
        }
    }
    #pragma unroll
    for (int q = 0; q < 16; q++) {
        float2 v = unpack2(acc[q]);
        g_hA[(size_t)(j0 + 2 * q)     * E_MAX + e] = silu(v.x);
        g_hA[(size_t)(j0 + 2 * q + 1) * E_MAX + e] = silu(v.y);
    }
}

// layers 2/3: 64 -> 64, J=16 slice (blockIdx.y of 4) x 2 edges/thread.
// per k-step: 4 LDS.128 + 2 LDG + 16 FFMA2. acc = 2x8 u64 = 32 regs.
__device__ __forceinline__ void layer_body16x2(const float* __restrict__ in_g,
                                               float* __restrict__ out_g,
                                               const float* __restrict__ Wg, int E) {
    __shared__ float ws[64 * 16];
    int tid = threadIdx.x;
    int j0 = blockIdx.y * 16;
    for (int i = tid; i < 64 * 16; i += 256) {
        int k = i >> 4, j = i & 15;
        ws[i] = Wg[k * 64 + j0 + j] * 0.125f;
    }
    __syncthreads();
    int e0 = blockIdx.x * 512 + tid;
    if (e0 >= E) return;
    int e1 = e0 + 256;
    int eB = min(e1, E - 1);   // duplicate store of E-1 writes same value -> benign

    unsigned long long acc0[8], acc1[8];
    #pragma unroll
    for (int q = 0; q < 8; q++) { acc0[q] = 0ULL; acc1[q] = 0ULL; }

    const float* p0 = in_g + e0;
    const float* p1 = in_g + eB;
    #pragma unroll 4
    for (int k = 0; k < 64; k++) {
        unsigned long long a = splat2(__ldg(p0)); p0 += E_MAX;
        unsigned long long b = splat2(__ldg(p1)); p1 += E_MAX;
        const ulonglong2* wp = (const ulonglong2*)(ws + k * 16);
        #pragma unroll
        for (int q = 0; q < 4; q++) {
            ulonglong2 w = wp[q];
            fma2(acc0[2 * q],     a, w.x);
            fma2(acc0[2 * q + 1], a, w.y);
            fma2(acc1[2 * q],     b, w.x);
            fma2(acc1[2 * q + 1], b, w.y);
        }
    }
    #pragma unroll
    for (int q = 0; q < 8; q++) {
        float2 v0 = unpack2(acc0[q]);
        float2 v1 = unpack2(acc1[q]);
        out_g[(size_t)(j0 + 2 * q)     * E_MAX + e0] = silu(v0.x);
        out_g[(size_t)(j0 + 2 * q + 1) * E_MAX + e0] = silu(v0.y);
        out_g[(size_t)(j0 + 2 * q)     * E_MAX + eB] = silu(v1.x);
        out_g[(size_t)(j0 + 2 * q + 1) * E_MAX + eB] = silu(v1.y);
    }
}

__global__ void __launch_bounds__(256, 4)
k_l2(const float* __restrict__ w2, int E) { layer_body16x2(g_hA, g_hB, w2, E); }

__global__ void __launch_bounds__(256, 4)
k_l3(const float* __restrict__ w3, int E) { layer_body16x2(g_hB, g_hA, w3, E); }

// layer 4: 64 -> 256. J=8 output slice (blockIdx.y of 32) x 4 EDGES/thread:
// per k-step 2 LDS.128 + 4 LDG + 16 FFMA2. acc = 4x4 u64 = 32 regs.
__global__ void __launch_bounds__(256, 4)
k_l4(const float* __restrict__ w4, int E) {
    __shared__ float ws[64 * 8];
    int tid = threadIdx.x;
    int j0 = blockIdx.y * 8;
    for (int i = tid; i < 64 * 8; i += 256) {
        int k = i >> 3, j = i & 7;
        ws[i] = w4[k * 256 + j0 + j] * 0.125f;
    }
    __syncthreads();
    int e0 = blockIdx.x * 1024 + tid;
    if (e0 >= E) return;
    int e1 = e0 + 256, e2 = e0 + 512, e3 = e0 + 768;
    int eB1 = min(e1, E - 1), eB2 = min(e2, E - 1), eB3 = min(e3, E - 1);

    unsigned long long acc0[4], acc1[4], acc2[4], acc3[4];
    #pragma unroll
    for (int q = 0; q < 4; q++) { acc0[q] = 0; acc1[q] = 0; acc2[q] = 0; acc3[q] = 0; }

    const float* p0 = g_hA + e0;
    const float* p1 = g_hA + eB1;
    const float* p2 = g_hA + eB2;
    const float* p3 = g_hA + eB3;
    #pragma unroll 4
    for (int k = 0; k < 64; k++) {
        unsigned long long a = splat2(__ldg(p0)); p0 += E_MAX;
        unsigned long long b = splat2(__ldg(p1)); p1 += E_MAX;
        unsigned long long c = splat2(__ldg(p2)); p2 += E_MAX;
        unsigned long long d = splat2(__ldg(p3)); p3 += E_MAX;
        const ulonglong2* wp = (const ulonglong2*)(ws + k * 8);
        ulonglong2 w0 = wp[0];
        ulonglong2 w1v = wp[1];
        fma2(acc0[0], a, w0.x); fma2(acc0[1], a, w0.y);
        fma2(acc0[2], a, w1v.x); fma2(acc0[3], a, w1v.y);
        fma2(acc1[0], b, w0.x); fma2(acc1[1], b, w0.y);
        fma2(acc1[2], b, w1v.x); fma2(acc1[3], b, w1v.y);
        fma2(acc2[0], c, w0.x); fma2(acc2[1], c, w0.y);
        fma2(acc2[2], c, w1v.x); fma2(acc2[3], c, w1v.y);
        fma2(acc3[0], d, w0.x); fma2(acc3[1], d, w0.y);
        fma2(acc3[2], d, w1v.x); fma2(acc3[3], d, w1v.y);
    }

    // packed u64 pairs are exactly two consecutive floats -> direct stores
    {
        ulonglong2* op = (ulonglong2*)(g_mix + (size_t)e0 * 256 + j0);
        op[0] = make_ulonglong2(acc0[0], acc0[1]);
        op[1] = make_ulonglong2(acc0[2], acc0[3]);
    }
    if (e1 < E) {
        ulonglong2* op = (ulonglong2*)(g_mix + (size_t)e1 * 256 + j0);
        op[0] = make_ulonglong2(acc1[0], acc1[1]);
        op[1] = make_ulonglong2(acc1[2], acc1[3]);
    }
    if (e2 < E) {
        ulonglong2* op = (ulonglong2*)(g_mix + (size_t)e2 * 256 + j0);
        op[0] = make_ulonglong2(acc2[0], acc2[1]);
        op[1] = make_ulonglong2(acc2[2], acc2[3]);
    }
    if (e3 < E) {
        ulonglong2* op = (ulonglong2*)(g_mix + (size_t)e3 * 256 + j0);
        op[0] = make_ulonglong2(acc3[0], acc3[1]);
        op[1] = make_ulonglong2(acc3[2], acc3[3]);
    }
}

// --------------------------------------------------- gather-side reduction
// warp per node; lane owns channels (2*lane, 2*lane+1); index prefetch.
__global__ void __launch_bounds__(256)
k_out(const float* __restrict__ node_feats, const int* __restrict__ senders,
      float* __restrict__ out, int N) {
    int w = threadIdx.x >> 5, lane = threadIdx.x & 31;
    int node = blockIdx.x * 8 + w;
    if (node >= N) return;
    int beg = g_start[node], end = g_start[node + 1];

    float acc[32];
    #pragma unroll
    for (int i = 0; i < 32; i++) acc[i] = 0.0f;

    int p = beg;
    int e = 0, snd = 0;
    if (p < end) { e = __ldg(g_esort + p); snd = __ldg(senders + e); }
    while (p < end) {
        int pn = p + 1;
        int en = 0, sndn = 0;
        if (pn < end) { en = __ldg(g_esort + pn); sndn = __ldg(senders + en); }

        const float2* mixp = (const float2*)(g_mix + (size_t)e * 256) + lane;
        const float4* yp = (const float4*)(g_y + (size_t)e * 16);
        float4 ya = __ldg(yp), yb = __ldg(yp + 1), yc = __ldg(yp + 2), yd = __ldg(yp + 3);
        float yv[15] = {ya.x, ya.y, ya.z, ya.w, yb.x, yb.y, yb.z, yb.w,
                        yc.x, yc.y, yc.z, yc.w, yd.x, yd.y, yd.z};
        float2 s  = __ldg((const float2*)(node_feats + (size_t)snd * 64) + lane);
        float2 m0 = __ldg(mixp);
        float2 m1 = __ldg(mixp + 32);
        float2 m2 = __ldg(mixp + 64);
        float2 m3 = __ldg(mixp + 96);
        float sm0[2] = {s.x * m0.x, s.y * m0.y};
        float sm1[2] = {s.x * m1.x, s.y * m1.y};
        float sm2[2] = {s.x * m2.x, s.y * m2.y};
        float sm3[2] = {s.x * m3.x, s.y * m3.y};
        #pragma unroll
        for (int h = 0; h < 2; h++) {
            float* a = acc + 16 * h;
            a[0] += sm0[h];
            a[1] = fmaf(sm1[h], yv[0], a[1]);
            a[2] = fmaf(sm1[h], yv[1], a[2]);
            a[3] = fmaf(sm1[h], yv[2], a[3]);
            #pragma unroll
            for (int m = 0; m < 5; m++) a[4 + m] = fmaf(sm2[h], yv[3 + m], a[4 + m]);
            #pragma unroll
            for (int m = 0; m < 7; m++) a[9 + m] = fmaf(sm3[h], yv[8 + m], a[9 + m]);
        }
        p = pn; e = en; snd = sndn;
    }

    // direct store in final output layout; lane owns c = 2*lane+h
    float* outp = out + (size_t)node * 1024;
    #pragma unroll
    for (int h = 0; h < 2; h++) {
        int c = 2 * lane + h;
        float* a = acc + 16 * h;
        outp[c] = a[0] * 0.25f;                                    // 1/sqrt(16)
        outp[64 + c * 3 + 0] = a[1] * 0.25f;
        outp[64 + c * 3 + 1] = a[2] * 0.25f;
        outp[64 + c * 3 + 2] = a[3] * 0.25f;
        #pragma unroll
        for (int m = 0; m < 5; m++) outp[256 + c * 5 + m] = a[4 + m] * 0.25f;
        #pragma unroll
        for (int m = 0; m < 7; m++) outp[576 + c * 7 + m] = a[9 + m] * 0.25f;
    }
}

// ---------------------------------------------------------------- launcher
extern "C" void kernel_launch(void* const* d_in, const int* in_sizes, int n_in,
                              void* d_out, int out_size) {
    const float* vectors    = (const float*)d_in[0];
    const float* node_feats = (const float*)d_in[1];
    const float* radial     = (const float*)d_in[2];
    const float* w1         = (const float*)d_in[3];
    const float* w2         = (const float*)d_in[4];
    const float* w3         = (const float*)d_in[5];
    const float* w4         = (const float*)d_in[6];
    const int*   senders    = (const int*)d_in[7];
    const int*   receivers  = (const int*)d_in[8];

    int E = in_sizes[7];
    int N = in_sizes[1] / 64;

    int gE  = (E + 255) / 256;
    int gM2 = (E + 511) / 512;
    int gM4 = (E + 1023) / 1024;
    // order: MLP chain first (l4 is launch #4 -> profiled slot); CSR + out after
    k_l1<<<dim3(gE, 2), 256>>>(radial, w1, E);
    k_l2<<<dim3(gM2, 4), 256>>>(w2, E);
    k_l3<<<dim3(gM2, 4), 256>>>(w3, E);
    k_l4<<<dim3(gM4, 32), 256>>>(w4, E);
    k_zero<<<(N + 1 + 255) / 256, 256>>>(N);
    k_y_hist<<<gE, 256>>>(vectors, receivers, E);
    k_scan<<<1, 1024>>>(N, E);
    k_scatter<<<gE, 256>>>(receivers, E);
    k_out<<<(N + 7) / 8, 256>>>(node_feats, senders, (float*)d_out, N);
}

// round 16
// speedup vs baseline: 1.0811x; 1.0811x over previous
#include <cuda_runtime.h>
#include <math.h>

#define E_MAX 160000
#define N_MAX 10000

// scratch (static __device__ -> allowed, no allocations)
__device__ float g_mix[(size_t)E_MAX * 256];   // per-edge radial MLP output
__device__ float g_hA[(size_t)64 * E_MAX];     // transposed activations [k][e]
__device__ float g_hB[(size_t)64 * E_MAX];
__device__ float g_y[(size_t)E_MAX * 16];      // per-edge Y_1(3),Y_2(5),Y_3(7),pad
__device__ int   g_count[N_MAX + 1];
__device__ int   g_start[N_MAX + 2];
__device__ int   g_cursor[N_MAX + 1];
__device__ int   g_esort[E_MAX];

// ---------------- packed f32x2 helpers (exact fp32, 2 FMAs / issue) ----------
__device__ __forceinline__ unsigned long long splat2(float x) {
    unsigned long long r;
    unsigned u = __float_as_uint(x);
    asm("mov.b64 %0, {%1, %1};" : "=l"(r) : "r"(u));
    return r;
}
__device__ __forceinline__ void fma2(unsigned long long& acc,
                                     unsigned long long a, unsigned long long b) {
    asm("fma.rn.f32x2 %0, %1, %2, %0;" : "+l"(acc) : "l"(a), "l"(b));
}
__device__ __forceinline__ float2 unpack2(unsigned long long v) {
    unsigned lo, hi;
    asm("mov.b64 {%0, %1}, %2;" : "=r"(lo), "=r"(hi) : "l"(v));
    return make_float2(__uint_as_float(lo), __uint_as_float(hi));
}
__device__ __forceinline__ float silu(float v) {
    return v * (1.0f / (1.0f + __expf(-v)));
}

// ---------------------------------------------------------------- zero counts
__global__ void k_zero(int n) {
    int i = blockIdx.x * blockDim.x + threadIdx.x;
    if (i <= n) g_count[i] = 0;
}

// ------------------------------------------- spherical harmonics + histogram
__global__ void k_y_hist(const float* __restrict__ vectors,
                         const int* __restrict__ receivers, int E) {
    int e = blockIdx.x * blockDim.x + threadIdx.x;
    if (e >= E) return;
    float x = vectors[3 * e + 0];
    float y = vectors[3 * e + 1];
    float z = vectors[3 * e + 2];
    float n2 = x * x + y * y + z * z;
    float inv = 1.0f / (sqrtf(n2) + 1e-12f);
    x *= inv; y *= inv; z *= inv;

    const float s3  = 1.7320508075688772f;
    const float s5  = 2.23606797749979f;
    const float s15 = 3.872983346207417f;
    const float c33 = 2.091650066335189f;
    const float c32 = 10.246950765959598f;
    const float c31 = 1.6201851746019651f;
    const float c30 = 1.3228756555322954f;

    float yv[16];
    yv[0] = s3 * y;  yv[1] = s3 * z;  yv[2] = s3 * x;
    yv[3] = s15 * x * y;
    yv[4] = s15 * y * z;
    yv[5] = 0.5f * s5 * (3.0f * z * z - 1.0f);
    yv[6] = s15 * x * z;
    yv[7] = 0.5f * s15 * (x * x - y * y);
    yv[8]  = c33 * y * (3.0f * x * x - y * y);
    yv[9]  = c32 * x * y * z;
    yv[10] = c31 * y * (5.0f * z * z - 1.0f);
    yv[11] = c30 * z * (5.0f * z * z - 3.0f);
    yv[12] = c31 * x * (5.0f * z * z - 1.0f);
    yv[13] = 0.5f * c32 * z * (x * x - y * y);
    yv[14] = c33 * x * (x * x - 3.0f * y * y);
    yv[15] = 1.0f;

    float4* o = (float4*)(g_y + (size_t)e * 16);
    o[0] = make_float4(yv[0], yv[1], yv[2], yv[3]);
    o[1] = make_float4(yv[4], yv[5], yv[6], yv[7]);
    o[2] = make_float4(yv[8], yv[9], yv[10], yv[11]);
    o[3] = make_float4(yv[12], yv[13], yv[14], yv[15]);

    atomicAdd(&g_count[receivers[e]], 1);
}

// ---------------------------------------------------------------- CSR scan
__global__ void k_scan(int n, int E) {
    __shared__ int sums[1024];
    int t = threadIdx.x;
    int chunk = (n + 1023) >> 10;
    int b = t * chunk;
    int eidx = min(b + chunk, n);
    int s = 0;
    for (int i = b; i < eidx; i++) s += g_count[i];
    sums[t] = s;
    __syncthreads();
    for (int off = 1; off < 1024; off <<= 1) {
        int v = (t >= off) ? sums[t - off] : 0;
        __syncthreads();
        sums[t] += v;
        __syncthreads();
    }
    int pre = (t > 0) ? sums[t - 1] : 0;
    for (int i = b; i < eidx; i++) {
        g_start[i]  = pre;
        g_cursor[i] = pre;
        pre += g_count[i];
    }
    if (t == 1023) g_start[n] = E;
}

// ---------------------------------------------------------------- scatter
__global__ void k_scatter(const int* __restrict__ receivers, int E) {
    int e = blockIdx.x * blockDim.x + threadIdx.x;
    if (e >= E) return;
    int p = atomicAdd(&g_cursor[receivers[e]], 1);
    g_esort[p] = e;
}

// -------------------------------------------------------------- MLP layers

// layer 1: 8 -> 64 (j-half per blockIdx.y), silu -> g_hA  (R12 structure)
__global__ void __launch_bounds__(256, 4)
k_l1(const float* __restrict__ radial, const float* __restrict__ w1, int E) {
    __shared__ float ws[8 * 32];
    int tid = threadIdx.x;
    int j0 = blockIdx.y * 32;
    if (tid < 256) {
        int k = tid >> 5, j = tid & 31;
        ws[tid] = w1[k * 64 + j0 + j] * 0.35355339059327379f;
    }
    __syncthreads();
    int e = blockIdx.x * 256 + tid;
    if (e >= E) return;

    const float4* rp = (const float4*)(radial + (size_t)e * 8);
    float4 a0 = __ldg(rp), a1 = __ldg(rp + 1);
    float r[8] = {a0.x, a0.y, a0.z, a0.w, a1.x, a1.y, a1.z, a1.w};

    unsigned long long acc[16];
    #pragma unroll
    for (int q = 0; q < 16; q++) acc[q] = 0ULL;
    #pragma unroll
    for (int k = 0; k < 8; k++) {
        unsigned long long a = splat2(r[k]);
        const ulonglong2* wp = (const ulonglong2*)(ws + k * 32);
        #pragma unroll
        for (int q = 0; q < 8; q++) {
            ulonglong2 w = wp[q];
            fma2(acc[2 * q],     a, w.x);
            fma2(acc[2 * q + 1], a, w.y);
        }
    }
    #pragma unroll
    for (int q = 0; q < 16; q++) {
        float2 v = unpack2(acc[q]);
        g_hA[(size_t)(j0 + 2 * q)     * E_MAX + e] = silu(v.x);
        g_hA[(size_t)(j0 + 2 * q + 1) * E_MAX + e] = silu(v.y);
    }
}

// layers 2/3: 64 -> 64, J=16 slice (blockIdx.y of 4) x 2 edges/thread.
// per k-step: 4 LDS.128 + 2 LDG + 16 FFMA2. acc = 2x8 u64 = 32 regs.
__device__ __forceinline__ void layer_body16x2(const float* __restrict__ in_g,
                                               float* __restrict__ out_g,
                                               const float* __restrict__ Wg, int E) {
    __shared__ float ws[64 * 16];
    int tid = threadIdx.x;
    int j0 = blockIdx.y * 16;
    for (int i = tid; i < 64 * 16; i += 256) {
        int k = i >> 4, j = i & 15;
        ws[i] = Wg[k * 64 + j0 + j] * 0.125f;
    }
    __syncthreads();
    int e0 = blockIdx.x * 512 + tid;
    if (e0 >= E) return;
    int e1 = e0 + 256;
    int eB = min(e1, E - 1);   // duplicate store of E-1 writes same value -> benign

    unsigned long long acc0[8], acc1[8];
    #pragma unroll
    for (int q = 0; q < 8; q++) { acc0[q] = 0ULL; acc1[q] = 0ULL; }

    const float* p0 = in_g + e0;
    const float* p1 = in_g + eB;
    #pragma unroll 4
    for (int k = 0; k < 64; k++) {
        unsigned long long a = splat2(__ldg(p0)); p0 += E_MAX;
        unsigned long long b = splat2(__ldg(p1)); p1 += E_MAX;
        const ulonglong2* wp = (const ulonglong2*)(ws + k * 16);
        #pragma unroll
        for (int q = 0; q < 4; q++) {
            ulonglong2 w = wp[q];
            fma2(acc0[2 * q],     a, w.x);
            fma2(acc0[2 * q + 1], a, w.y);
            fma2(acc1[2 * q],     b, w.x);
            fma2(acc1[2 * q + 1], b, w.y);
        }
    }
    #pragma unroll
    for (int q = 0; q < 8; q++) {
        float2 v0 = unpack2(acc0[q]);
        float2 v1 = unpack2(acc1[q]);
        out_g[(size_t)(j0 + 2 * q)     * E_MAX + e0] = silu(v0.x);
        out_g[(size_t)(j0 + 2 * q + 1) * E_MAX + e0] = silu(v0.y);
        out_g[(size_t)(j0 + 2 * q)     * E_MAX + eB] = silu(v1.x);
        out_g[(size_t)(j0 + 2 * q + 1) * E_MAX + eB] = silu(v1.y);
    }
}

__global__ void __launch_bounds__(256, 4)
k_l2(const float* __restrict__ w2, int E) { layer_body16x2(g_hA, g_hB, w2, E); }

__global__ void __launch_bounds__(256, 4)
k_l3(const float* __restrict__ w3, int E) { layer_body16x2(g_hB, g_hA, w3, E); }

// layer 4: 64 -> 256. J=16 output slice (blockIdx.y of 16) x 2 EDGES/thread
// (the R14 measured-best config: 160.5us): per k-step 4 LDS.128 + 2 LDG +
// 16 FFMA2; h re-read 16x. acc = 2x8 u64 = 32 regs; 32 warps/SM.
__global__ void __launch_bounds__(256, 4)
k_l4(const float* __restrict__ w4, int E) {
    __shared__ float ws[64 * 16];
    int tid = threadIdx.x;
    int j0 = blockIdx.y * 16;
    for (int i = tid; i < 64 * 16; i += 256) {
        int k = i >> 4, j = i & 15;
        ws[i] = w4[k * 256 + j0 + j] * 0.125f;
    }
    __syncthreads();
    int e0 = blockIdx.x * 512 + tid;
    if (e0 >= E) return;
    int e1 = e0 + 256;
    int eB = min(e1, E - 1);   // duplicate loads of edge E-1 are benign

    unsigned long long acc0[8], acc1[8];
    #pragma unroll
    for (int q = 0; q < 8; q++) { acc0[q] = 0ULL; acc1[q] = 0ULL; }

    const float* p0 = g_hA + e0;
    const float* p1 = g_hA + eB;
    #pragma unroll 4
    for (int k = 0; k < 64; k++) {
        unsigned long long a = splat2(__ldg(p0)); p0 += E_MAX;
        unsigned long long b = splat2(__ldg(p1)); p1 += E_MAX;
        const ulonglong2* wp = (const ulonglong2*)(ws + k * 16);
        #pragma unroll
        for (int q = 0; q < 4; q++) {
            ulonglong2 w = wp[q];
            fma2(acc0[2 * q],     a, w.x);
            fma2(acc0[2 * q + 1], a, w.y);
            fma2(acc1[2 * q],     b, w.x);
            fma2(acc1[2 * q + 1], b, w.y);
        }
    }

    // packed u64 pairs are exactly two consecutive floats -> direct stores
    {
        ulonglong2* op = (ulonglong2*)(g_mix + (size_t)e0 * 256 + j0);
        #pragma unroll
        for (int q = 0; q < 4; q++)
            op[q] = make_ulonglong2(acc0[2 * q], acc0[2 * q + 1]);
    }
    if (e1 < E) {
        ulonglong2* op = (ulonglong2*)(g_mix + (size_t)e1 * 256 + j0);
        #pragma unroll
        for (int q = 0; q < 4; q++)
            op[q] = make_ulonglong2(acc1[2 * q], acc1[2 * q + 1]);
    }
}

// --------------------------------------------------- gather-side reduction
// warp per node; lane owns channels (2*lane, 2*lane+1); index prefetch.
__global__ void __launch_bounds__(256)
k_out(const float* __restrict__ node_feats, const int* __restrict__ senders,
      float* __restrict__ out, int N) {
    int w = threadIdx.x >> 5, lane = threadIdx.x & 31;
    int node = blockIdx.x * 8 + w;
    if (node >= N) return;
    int beg = g_start[node], end = g_start[node + 1];

    float acc[32];
    #pragma unroll
    for (int i = 0; i < 32; i++) acc[i] = 0.0f;

    int p = beg;
    int e = 0, snd = 0;
    if (p < end) { e = __ldg(g_esort + p); snd = __ldg(senders + e); }
    while (p < end) {
        int pn = p + 1;
        int en = 0, sndn = 0;
        if (pn < end) { en = __ldg(g_esort + pn); sndn = __ldg(senders + en); }

        const float2* mixp = (const float2*)(g_mix + (size_t)e * 256) + lane;
        const float4* yp = (const float4*)(g_y + (size_t)e * 16);
        float4 ya = __ldg(yp), yb = __ldg(yp + 1), yc = __ldg(yp + 2), yd = __ldg(yp + 3);
        float yv[15] = {ya.x, ya.y, ya.z, ya.w, yb.x, yb.y, yb.z, yb.w,
                        yc.x, yc.y, yc.z, yc.w, yd.x, yd.y, yd.z};
        float2 s  = __ldg((const float2*)(node_feats + (size_t)snd * 64) + lane);
        float2 m0 = __ldg(mixp);
        float2 m1 = __ldg(mixp + 32);
        float2 m2 = __ldg(mixp + 64);
        float2 m3 = __ldg(mixp + 96);
        float sm0[2] = {s.x * m0.x, s.y * m0.y};
        float sm1[2] = {s.x * m1.x, s.y * m1.y};
        float sm2[2] = {s.x * m2.x, s.y * m2.y};
        float sm3[2] = {s.x * m3.x, s.y * m3.y};
        #pragma unroll
        for (int h = 0; h < 2; h++) {
            float* a = acc + 16 * h;
            a[0] += sm0[h];
            a[1] = fmaf(sm1[h], yv[0], a[1]);
            a[2] = fmaf(sm1[h], yv[1], a[2]);
            a[3] = fmaf(sm1[h], yv[2], a[3]);
            #pragma unroll
            for (int m = 0; m < 5; m++) a[4 + m] = fmaf(sm2[h], yv[3 + m], a[4 + m]);
            #pragma unroll
            for (int m = 0; m < 7; m++) a[9 + m] = fmaf(sm3[h], yv[8 + m], a[9 + m]);
        }
        p = pn; e = en; snd = sndn;
    }

    // direct store in final output layout; lane owns c = 2*lane+h
    float* outp = out + (size_t)node * 1024;
    #pragma unroll
    for (int h = 0; h < 2; h++) {
        int c = 2 * lane + h;
        float* a = acc + 16 * h;
        outp[c] = a[0] * 0.25f;                                    // 1/sqrt(16)
        outp[64 + c * 3 + 0] = a[1] * 0.25f;
        outp[64 + c * 3 + 1] = a[2] * 0.25f;
        outp[64 + c * 3 + 2] = a[3] * 0.25f;
        #pragma unroll
        for (int m = 0; m < 5; m++) outp[256 + c * 5 + m] = a[4 + m] * 0.25f;
        #pragma unroll
        for (int m = 0; m < 7; m++) outp[576 + c * 7 + m] = a[9 + m] * 0.25f;
    }
}

// ---------------------------------------------------------------- launcher
extern "C" void kernel_launch(void* const* d_in, const int* in_sizes, int n_in,
                              void* d_out, int out_size) {
    const float* vectors    = (const float*)d_in[0];
    const float* node_feats = (const float*)d_in[1];
    const float* radial     = (const float*)d_in[2];
    const float* w1         = (const float*)d_in[3];
    const float* w2         = (const float*)d_in[4];
    const float* w3         = (const float*)d_in[5];
    const float* w4         = (const float*)d_in[6];
    const int*   senders    = (const int*)d_in[7];
    const int*   receivers  = (const int*)d_in[8];

    int E = in_sizes[7];
    int N = in_sizes[1] / 64;

    int gE  = (E + 255) / 256;
    int gM2 = (E + 511) / 512;
    // order: MLP chain first (l4 is launch #4 -> profiled slot); CSR + out after
    k_l1<<<dim3(gE, 2), 256>>>(radial, w1, E);
    k_l2<<<dim3(gM2, 4), 256>>>(w2, E);
    k_l3<<<dim3(gM2, 4), 256>>>(w3, E);
    k_l4<<<dim3(gM2, 16), 256>>>(w4, E);
    k_zero<<<(N + 1 + 255) / 256, 256>>>(N);
    k_y_hist<<<gE, 256>>>(vectors, receivers, E);
    k_scan<<<1, 1024>>>(N, E);
    k_scatter<<<gE, 256>>>(receivers, E);
    k_out<<<(N + 7) / 8, 256>>>(node_feats, senders, (float*)d_out, N);
}